// round 10
// baseline (speedup 1.0000x reference)
#include <cuda_runtime.h>
#include <cuda_fp16.h>
#include <cstdint>
#include <cstddef>

#define D_DIM   1024
#define NBATCH  16

#define BM 128
#define BN 128
#define BK 64
#define NSTG 2
#define NITER (D_DIM / BK)               // 16

#define TILE_BYTES  (BM * 128)           // 16 KB
#define STAGE_BYTES (2 * TILE_BYTES)     // 32 KB
#define SMEM_BYTES  (NSTG * STAGE_BYTES) // 64 KB

#define SLOTS       444                  // 3 CTAs/SM * 148 SMs (exact capacity)
#define PROD_CTAS   148
#define PROD_WARPS  (PROD_CTAS * 4)      // 592
#define PAIR_UNITS  (NBATCH * 1024)      // 16384 (each = 2 rows)
#define PAIRS_PER_BATCH 1024

#define FULL_ITEMS  888                  // full 128x128 tiles
#define TOTAL_ITEMS 1160                 // + 272 half-N (128x64) tail items

// fp16 normalized-row scratch + sync state (allocation-free; zero-init,
// self-resetting at kernel end so graph replays see clean state)
__device__ __half g_ra[(size_t)NBATCH * D_DIM * D_DIM];
__device__ __half g_rb[(size_t)NBATCH * D_DIM * D_DIM];
__device__ int    g_cnt[NBATCH];
__device__ int    g_tile;
__device__ int    g_done;

// ---------------------------------------------------------------- helpers
static __device__ __forceinline__ uint32_t smem_u32(const void* p) {
    uint32_t a;
    asm("{ .reg .u64 t; cvta.to.shared.u64 t, %1; cvt.u32.u64 %0, t; }"
        : "=r"(a) : "l"(p));
    return a;
}
static __device__ __forceinline__ uint32_t sw128(uint32_t o) {
    return o ^ ((o >> 3) & 0x70u);
}
static __device__ __forceinline__ void cp16(uint32_t dst, const void* src) {
    asm volatile("cp.async.cg.shared.global [%0], [%1], 16;"
                 :: "r"(dst), "l"(src) : "memory");
}
static __device__ __forceinline__ void ldmatrix_x4(uint32_t* r, uint32_t addr) {
    asm volatile("ldmatrix.sync.aligned.m8n8.x4.shared.b16 {%0,%1,%2,%3}, [%4];"
                 : "=r"(r[0]), "=r"(r[1]), "=r"(r[2]), "=r"(r[3]) : "r"(addr));
}
static __device__ __forceinline__ void mma16816(float* d, const uint32_t* a,
                                                const uint32_t* b) {
    asm volatile(
        "mma.sync.aligned.m16n8k16.row.col.f32.f16.f16.f32 "
        "{%0,%1,%2,%3}, {%4,%5,%6,%7}, {%8,%9}, {%0,%1,%2,%3};"
        : "+f"(d[0]), "+f"(d[1]), "+f"(d[2]), "+f"(d[3])
        : "r"(a[0]), "r"(a[1]), "r"(a[2]), "r"(a[3]), "r"(b[0]), "r"(b[1]));
}

// ---------------------------------------------------------------- producer
// One warp normalizes rows u and u+1 of batch k (u even, in [0,2048);
// u<1024 -> a-row u, else b-row u-1024).
static __device__ void norm_pair(const float* __restrict__ a,
                                 const float* __restrict__ b,
                                 const float* __restrict__ w,
                                 int k, int u, int lane) {
    const float4* w4 = reinterpret_cast<const float4*>(w);
    const float* s0 = (u < 1024) ? a : b;
    const float* s1 = (u + 1 < 1024) ? a : b;
    __half* d0 = (u < 1024) ? g_ra : g_rb;
    __half* d1 = (u + 1 < 1024) ? g_ra : g_rb;
    const size_t r0 = (size_t)k * 1024 + (u & 1023);
    const size_t r1 = (size_t)k * 1024 + ((u + 1) & 1023);
    const float4* p0 = reinterpret_cast<const float4*>(s0 + r0 * D_DIM);
    const float4* p1 = reinterpret_cast<const float4*>(s1 + r1 * D_DIM);

    float4 va[8], vb[8];
    float sa = 0.f, sb = 0.f;
#pragma unroll
    for (int j = 0; j < 8; j++) {
        float4 ww = w4[lane + 32 * j];
        float4 x0 = p0[lane + 32 * j];
        float4 x1 = p1[lane + 32 * j];
        va[j].x = x0.x * ww.x; va[j].y = x0.y * ww.y;
        va[j].z = x0.z * ww.z; va[j].w = x0.w * ww.w;
        vb[j].x = x1.x * ww.x; vb[j].y = x1.y * ww.y;
        vb[j].z = x1.z * ww.z; vb[j].w = x1.w * ww.w;
        sa += va[j].x * va[j].x + va[j].y * va[j].y
            + va[j].z * va[j].z + va[j].w * va[j].w;
        sb += vb[j].x * vb[j].x + vb[j].y * vb[j].y
            + vb[j].z * vb[j].z + vb[j].w * vb[j].w;
    }
#pragma unroll
    for (int o = 16; o > 0; o >>= 1) {
        sa += __shfl_xor_sync(0xFFFFFFFFu, sa, o);
        sb += __shfl_xor_sync(0xFFFFFFFFu, sb, o);
    }
    const float c0 = rsqrtf(fmaxf(sa, 1e-12f));
    const float c1 = rsqrtf(fmaxf(sb, 1e-12f));

    struct alignas(8) H4 { __half2 a, b; };
    {
        H4* q = reinterpret_cast<H4*>(d0 + r0 * D_DIM);
#pragma unroll
        for (int j = 0; j < 8; j++) {
            H4 h;
            h.a = __floats2half2_rn(va[j].x * c0, va[j].y * c0);
            h.b = __floats2half2_rn(va[j].z * c0, va[j].w * c0);
            q[lane + 32 * j] = h;
        }
    }
    {
        H4* q = reinterpret_cast<H4*>(d1 + r1 * D_DIM);
#pragma unroll
        for (int j = 0; j < 8; j++) {
            H4 h;
            h.a = __floats2half2_rn(vb[j].x * c1, vb[j].y * c1);
            h.b = __floats2half2_rn(vb[j].z * c1, vb[j].w * c1);
            q[lane + 32 * j] = h;
        }
    }
}

// ---------------------------------------------------------------- GEMM core
template <int BROWS>
static __device__ __forceinline__ void load_stage(uint32_t stg,
                                                  const __half* gA, const __half* gB,
                                                  int kof, int tid) {
#pragma unroll
    for (int i = 0; i < 8; i++) {            // A: 128 rows x 8 segs
        int q = i * 128 + tid;
        int row = q >> 3;
        int colb = (q & 7) * 16;
        cp16(stg + sw128((uint32_t)(row * 128 + colb)),
             (const char*)(gA + (size_t)row * D_DIM + kof) + colb);
    }
#pragma unroll
    for (int i = 0; i < BROWS / 16; i++) {   // B: BROWS rows x 8 segs
        int q = i * 128 + tid;
        int row = q >> 3;
        int colb = (q & 7) * 16;
        cp16(stg + TILE_BYTES + sw128((uint32_t)(row * 128 + colb)),
             (const char*)(gB + (size_t)row * D_DIM + kof) + colb);
    }
    asm volatile("cp.async.commit_group;" ::: "memory");
}

// NQ = n16 blocks per warp (4 = full 128x128 tile, 2 = half 128x64 tile).
template <int NQ>
static __device__ __forceinline__ void compute_tile(uint32_t sb,
                                                    const __half* gA,
                                                    const __half* gB,
                                                    float* oB,
                                                    int bm0, int bn0, int tid) {
    const int wid  = tid >> 5;
    const int lane = tid & 31;
    const int wm   = wid & 1;
    const int wn   = wid >> 1;

    const int aRow  = lane & 15;
    const int aColb = (lane >> 4) << 4;
    const int bRow  = ((lane >> 4) << 3) + (lane & 7);
    const int bColb = ((lane >> 3) & 1) << 4;

    uint32_t aOff[4], bOff[NQ];
#pragma unroll
    for (int mt = 0; mt < 4; mt++)
        aOff[mt] = sw128((uint32_t)((wm * 64 + mt * 16 + aRow) * 128 + aColb));
#pragma unroll
    for (int nq = 0; nq < NQ; nq++)
        bOff[nq] = sw128((uint32_t)((wn * (NQ * 16) + nq * 16 + bRow) * 128 + bColb))
                 + TILE_BYTES;

    float acc[4][2 * NQ][4];
#pragma unroll
    for (int i = 0; i < 4; i++)
#pragma unroll
        for (int j = 0; j < 2 * NQ; j++)
#pragma unroll
            for (int v = 0; v < 4; v++) acc[i][j][v] = 0.0f;

    load_stage<NQ * 32>(sb + 0 * STAGE_BYTES, gA, gB, 0 * BK, tid);
    load_stage<NQ * 32>(sb + 1 * STAGE_BYTES, gA, gB, 1 * BK, tid);

    for (int it = 0; it < NITER; it++) {
        // Newest committed group is chunk it+1's (or empty tail), so
        // wait_group 1 guarantees chunk it is fully resident.
        asm volatile("cp.async.wait_group 1;" ::: "memory");
        __syncthreads();

        const uint32_t sT = sb + (it & 1) * STAGE_BYTES;

#pragma unroll
        for (int kk = 0; kk < 4; kk++) {
            const uint32_t kb = kk * 32;
            uint32_t af[4][4];
#pragma unroll
            for (int mt = 0; mt < 4; mt++)
                ldmatrix_x4(af[mt], sT + (aOff[mt] ^ kb));
#pragma unroll
            for (int nq = 0; nq < NQ; nq++) {
                uint32_t bf[4];
                ldmatrix_x4(bf, sT + (bOff[nq] ^ kb));
#pragma unroll
                for (int mt = 0; mt < 4; mt++) {
                    mma16816(acc[mt][2 * nq + 0], af[mt], bf + 0);
                    mma16816(acc[mt][2 * nq + 1], af[mt], bf + 2);
                }
            }
        }

        __syncthreads();                     // all warps done reading stage it&1
        if (it + 2 < NITER)
            load_stage<NQ * 32>(sT, gA, gB, (it + 2) * BK, tid);
        else
            asm volatile("cp.async.commit_group;" ::: "memory");
    }

#pragma unroll
    for (int mt = 0; mt < 4; mt++) {
        int row = bm0 + wm * 64 + mt * 16 + (lane >> 2);
#pragma unroll
        for (int nt = 0; nt < 2 * NQ; nt++) {
            int col = bn0 + wn * (NQ * 16) + nt * 8 + (lane & 3) * 2;
            *reinterpret_cast<float2*>(oB + (size_t)row * D_DIM + col) =
                make_float2(acc[mt][nt][0], acc[mt][nt][1]);
            *reinterpret_cast<float2*>(oB + (size_t)(row + 8) * D_DIM + col) =
                make_float2(acc[mt][nt][2], acc[mt][nt][3]);
        }
    }
}

// ---------------------------------------------------------------- fused kernel
// CTAs 0..147: normalize (batch-interleaved, 2 rows per warp per round), then
// join the consumer pool. CTAs 148..443: consume immediately from an atomic
// tile queue, gated by per-batch counters. Grid = exact residency capacity
// (launch_bounds(128,3)) -> no pending-CTA deadlock. Last CTA out resets state.
__global__ void __launch_bounds__(128, 3) fused_kernel(const float* __restrict__ a,
                                                       const float* __restrict__ b,
                                                       const float* __restrict__ w,
                                                       float* __restrict__ out) {
    extern __shared__ char smem[];
    const uint32_t sb = smem_u32(smem);
    const int tid  = threadIdx.x;
    const int wid  = tid >> 5;
    const int lane = tid & 31;

    // -------- producer phase
    if (blockIdx.x < PROD_CTAS) {
        const int gw = blockIdx.x * 4 + wid;      // 0..591
#pragma unroll 1
        for (int j = 0; j < 28; j++) {
            const int p = gw + PROD_WARPS * j;    // pair-unit, batch-major
            if (p < PAIR_UNITS) {
                const int k = p >> 10;
                const int u = (p & 1023) * 2;
                norm_pair(a, b, w, k, u, lane);
                __syncwarp();
                if (lane == 0) {
                    __threadfence();
                    atomicAdd(&g_cnt[k], 1);
                }
            }
        }
        __syncthreads();                          // whole CTA done producing
    }

    // -------- consumer phase
    __shared__ int s_t;
    while (true) {
        __syncthreads();                          // protects s_t + smem reuse
        if (tid == 0) s_t = atomicAdd(&g_tile, 1);
        __syncthreads();
        const int item = s_t;
        if (item >= TOTAL_ITEMS) break;

        int t, bn0;
        bool half;
        if (item < FULL_ITEMS) {
            t = item; bn0 = (t & 7) * BN; half = false;
        } else {
            int j = item - FULL_ITEMS;
            t = FULL_ITEMS + (j >> 1);
            bn0 = (t & 7) * BN + (j & 1) * 64;
            half = true;
        }
        const int batch = t >> 6;
        const int bm0 = ((t >> 3) & 7) * BM;

        if (tid == 0) {
            while (atomicAdd(&g_cnt[batch], 0) < PAIRS_PER_BATCH) __nanosleep(128);
            __threadfence();
        }
        __syncthreads();

        const __half* gA = g_ra + (size_t)batch * (D_DIM * D_DIM) + (size_t)bm0 * D_DIM;
        const __half* gB = g_rb + (size_t)batch * (D_DIM * D_DIM) + (size_t)bn0 * D_DIM;
        float* oB = out + (size_t)batch * (D_DIM * D_DIM);

        if (!half)
            compute_tile<4>(sb, gA, gB, oB, bm0, bn0, tid);
        else
            compute_tile<2>(sb, gA, gB, oB, bm0, bn0, tid);
    }

    // -------- self-reset by the last CTA to finish (replay-safe state)
    __syncthreads();
    if (tid == 0) {
        const int d = atomicAdd(&g_done, 1);
        if (d == SLOTS - 1) {
#pragma unroll
            for (int k = 0; k < NBATCH; k++) g_cnt[k] = 0;
            g_tile = 0;
            __threadfence();
            g_done = 0;
        }
    }
}

// ---------------------------------------------------------------- launch
extern "C" void kernel_launch(void* const* d_in, const int* in_sizes, int n_in,
                              void* d_out, int out_size) {
    const float* a = (const float*)d_in[0];
    const float* b = (const float*)d_in[1];
    const float* w = (const float*)d_in[2];
    float* out = (float*)d_out;

    cudaFuncSetAttribute(fused_kernel, cudaFuncAttributeMaxDynamicSharedMemorySize,
                         SMEM_BYTES);
    fused_kernel<<<SLOTS, 128, SMEM_BYTES>>>(a, b, w, out);
}

// round 11
// speedup vs baseline: 1.2107x; 1.2107x over previous
#include <cuda_runtime.h>
#include <cuda_fp16.h>
#include <cstdint>
#include <cstddef>

#define D_DIM   1024
#define NBATCH  16
#define NROWS   (NBATCH * D_DIM)

#define BM 128
#define BN 128
#define BK 64                  // fp16 per K-chunk = 128B row (SW128)
#define NSTG 3
#define NITER (D_DIM / BK)     // 16

#define TILE_BYTES  (BM * 128)           // 16 KB
#define STAGE_BYTES (2 * TILE_BYTES)     // 32 KB
#define SMEM_BYTES  (NSTG * STAGE_BYTES) // 96 KB

// fp16 normalized-row scratch (allocation-free: __device__ globals)
__device__ __half g_ra[(size_t)NBATCH * D_DIM * D_DIM];
__device__ __half g_rb[(size_t)NBATCH * D_DIM * D_DIM];

// ---------------------------------------------------------------- helpers
static __device__ __forceinline__ uint32_t smem_u32(const void* p) {
    uint32_t a;
    asm("{ .reg .u64 t; cvta.to.shared.u64 t, %1; cvt.u32.u64 %0, t; }"
        : "=r"(a) : "l"(p));
    return a;
}
static __device__ __forceinline__ uint32_t sw128(uint32_t o) {
    return o ^ ((o >> 3) & 0x70u);
}
static __device__ __forceinline__ void cp16(uint32_t dst, const void* src) {
    asm volatile("cp.async.cg.shared.global [%0], [%1], 16;"
                 :: "r"(dst), "l"(src) : "memory");
}
static __device__ __forceinline__ void ldmatrix_x4(uint32_t* r, uint32_t addr) {
    asm volatile("ldmatrix.sync.aligned.m8n8.x4.shared.b16 {%0,%1,%2,%3}, [%4];"
                 : "=r"(r[0]), "=r"(r[1]), "=r"(r[2]), "=r"(r[3]) : "r"(addr));
}
static __device__ __forceinline__ void mma16816(float* d, const uint32_t* a,
                                                const uint32_t* b) {
    asm volatile(
        "mma.sync.aligned.m16n8k16.row.col.f32.f16.f16.f32 "
        "{%0,%1,%2,%3}, {%4,%5,%6,%7}, {%8,%9}, {%0,%1,%2,%3};"
        : "+f"(d[0]), "+f"(d[1]), "+f"(d[2]), "+f"(d[3])
        : "r"(a[0]), "r"(a[1]), "r"(a[2]), "r"(a[3]), "r"(b[0]), "r"(b[1]));
}

// ---------------------------------------------------------------- normalize
__global__ void __launch_bounds__(128) norm_kernel(const float* __restrict__ a,
                                                   const float* __restrict__ b,
                                                   const float* __restrict__ w) {
    const int row = blockIdx.x;
    const float* src = (blockIdx.y == 0) ? a : b;
    __half* dst = (blockIdx.y == 0) ? g_ra : g_rb;
    const int t = threadIdx.x;

    const float4* s4 = reinterpret_cast<const float4*>(src + (size_t)row * D_DIM);
    const float4* w4 = reinterpret_cast<const float4*>(w);

    float4 x0 = s4[t];       float4 w0 = w4[t];
    float4 x1 = s4[t + 128]; float4 w1 = w4[t + 128];
    float4 v0, v1;
    v0.x = x0.x * w0.x; v0.y = x0.y * w0.y; v0.z = x0.z * w0.z; v0.w = x0.w * w0.w;
    v1.x = x1.x * w1.x; v1.y = x1.y * w1.y; v1.z = x1.z * w1.z; v1.w = x1.w * w1.w;

    float sum = v0.x * v0.x + v0.y * v0.y + v0.z * v0.z + v0.w * v0.w
              + v1.x * v1.x + v1.y * v1.y + v1.z * v1.z + v1.w * v1.w;
#pragma unroll
    for (int o = 16; o > 0; o >>= 1) sum += __shfl_xor_sync(0xFFFFFFFFu, sum, o);

    __shared__ float red[4];
    if ((t & 31) == 0) red[t >> 5] = sum;
    __syncthreads();
    float tot = red[0] + red[1] + red[2] + red[3];
    float s = rsqrtf(fmaxf(tot, 1e-12f));

    __half2* d2 = reinterpret_cast<__half2*>(dst + (size_t)row * D_DIM);
    d2[2 * t + 0]         = __floats2half2_rn(v0.x * s, v0.y * s);
    d2[2 * t + 1]         = __floats2half2_rn(v0.z * s, v0.w * s);
    d2[2 * (t + 128) + 0] = __floats2half2_rn(v1.x * s, v1.y * s);
    d2[2 * (t + 128) + 1] = __floats2half2_rn(v1.z * s, v1.w * s);
}

// ---------------------------------------------------------------- GEMM
// 128x128 block tile, 4 warps (64x64 each), NSTG=3, single barrier/iter,
// register double-buffered fragments (launch_bounds(128,2) => 256-reg budget).
static __device__ __forceinline__ void load_stage(uint32_t stg,
                                                  const __half* gA, const __half* gB,
                                                  int kof, int tid) {
#pragma unroll
    for (int i = 0; i < 8; i++) {
        int q = i * 128 + tid;      // 1024 16B segments per operand tile
        int row = q >> 3;
        int colb = (q & 7) * 16;
        uint32_t so = sw128((uint32_t)(row * 128 + colb));
        cp16(stg + so,              (const char*)(gA + (size_t)row * D_DIM + kof) + colb);
        cp16(stg + TILE_BYTES + so, (const char*)(gB + (size_t)row * D_DIM + kof) + colb);
    }
    asm volatile("cp.async.commit_group;" ::: "memory");
}

__global__ void __launch_bounds__(128, 2) gemm_kernel(float* __restrict__ out) {
    extern __shared__ char smem[];
    const uint32_t sb = smem_u32(smem);
    const int tid  = threadIdx.x;
    const int wid  = tid >> 5;
    const int lane = tid & 31;
    const int wm   = wid & 1;        // 2 warps along M: 64 rows each
    const int wn   = wid >> 1;       // 2 warps along N: 64 cols each
    const int bn0   = blockIdx.x * BN;
    const int bm0   = blockIdx.y * BM;
    const int batch = blockIdx.z;

    const __half* gA = g_ra + (size_t)batch * (D_DIM * D_DIM) + (size_t)bm0 * D_DIM;
    const __half* gB = g_rb + (size_t)batch * (D_DIM * D_DIM) + (size_t)bn0 * D_DIM;

    float acc[4][8][4];
#pragma unroll
    for (int i = 0; i < 4; i++)
#pragma unroll
        for (int j = 0; j < 8; j++)
#pragma unroll
            for (int v = 0; v < 4; v++) acc[i][j][v] = 0.0f;

    // Swizzled ldmatrix bases; kb = kk*32 occupies bits 5-6 which are zero in
    // the unswizzled base, so sw128(base+kb) == sw128(base) ^ kb.
    const int aRow  = lane & 15;
    const int aColb = (lane >> 4) << 4;
    const int bRow  = ((lane >> 4) << 3) + (lane & 7);
    const int bColb = ((lane >> 3) & 1) << 4;

    uint32_t aOff[4], bOff[4];
#pragma unroll
    for (int mt = 0; mt < 4; mt++)
        aOff[mt] = sw128((uint32_t)((wm * 64 + mt * 16 + aRow) * 128 + aColb));
#pragma unroll
    for (int nq = 0; nq < 4; nq++)
        bOff[nq] = sw128((uint32_t)((wn * 64 + nq * 16 + bRow) * 128 + bColb))
                 + TILE_BYTES;

    // Double-buffered fragments
    uint32_t af[2][4][4], bf[2][4][4];

#define LD_FRAGS(buf, sT, kk)                                              \
    do {                                                                   \
        const uint32_t kb_ = (kk) * 32;                                    \
        _Pragma("unroll")                                                  \
        for (int mt_ = 0; mt_ < 4; mt_++)                                  \
            ldmatrix_x4(af[buf][mt_], (sT) + (aOff[mt_] ^ kb_));           \
        _Pragma("unroll")                                                  \
        for (int nq_ = 0; nq_ < 4; nq_++)                                  \
            ldmatrix_x4(bf[buf][nq_], (sT) + (bOff[nq_] ^ kb_));           \
    } while (0)

#define MMA_ALL(buf)                                                       \
    do {                                                                   \
        _Pragma("unroll")                                                  \
        for (int nq_ = 0; nq_ < 4; nq_++)                                  \
            _Pragma("unroll")                                              \
            for (int mt_ = 0; mt_ < 4; mt_++) {                            \
                mma16816(acc[mt_][2 * nq_ + 0], af[buf][mt_],              \
                         &bf[buf][nq_][0]);                                \
                mma16816(acc[mt_][2 * nq_ + 1], af[buf][mt_],              \
                         &bf[buf][nq_][2]);                                \
            }                                                              \
    } while (0)

    // prologue: 2 stages in flight
    load_stage(sb + 0 * STAGE_BYTES, gA, gB, 0 * BK, tid);
    load_stage(sb + 1 * STAGE_BYTES, gA, gB, 1 * BK, tid);

    for (int it = 0; it < NITER; it++) {
        // Pending groups: chunks it, it+1 (<=2). wait_group 1 => chunk it
        // resident. Single barrier: stage (it+2)%3 == (it-1)%3 was fully read
        // during iter it-1, and every warp passed this barrier since.
        asm volatile("cp.async.wait_group 1;" ::: "memory");
        __syncthreads();

        if (it + 2 < NITER)
            load_stage(sb + ((it + 2) % NSTG) * STAGE_BYTES, gA, gB, (it + 2) * BK, tid);
        else
            asm volatile("cp.async.commit_group;" ::: "memory");

        const uint32_t sT = sb + (it % NSTG) * STAGE_BYTES;

        // software-pipelined fragment schedule: LDSM(kk+1) before MMA(kk)
        LD_FRAGS(0, sT, 0);
        LD_FRAGS(1, sT, 1);
        MMA_ALL(0);
        LD_FRAGS(0, sT, 2);
        MMA_ALL(1);
        LD_FRAGS(1, sT, 3);
        MMA_ALL(0);
        MMA_ALL(1);
    }

    // epilogue: c0,c1 -> (m = lane>>2, n = (lane&3)*2); c2,c3 -> m+8
    float* oB = out + (size_t)batch * (D_DIM * D_DIM);
#pragma unroll
    for (int mt = 0; mt < 4; mt++) {
        int row = bm0 + wm * 64 + mt * 16 + (lane >> 2);
#pragma unroll
        for (int nt = 0; nt < 8; nt++) {
            int col = bn0 + wn * 64 + nt * 8 + (lane & 3) * 2;
            *reinterpret_cast<float2*>(oB + (size_t)row * D_DIM + col) =
                make_float2(acc[mt][nt][0], acc[mt][nt][1]);
            *reinterpret_cast<float2*>(oB + (size_t)(row + 8) * D_DIM + col) =
                make_float2(acc[mt][nt][2], acc[mt][nt][3]);
        }
    }
}

// ---------------------------------------------------------------- launch
extern "C" void kernel_launch(void* const* d_in, const int* in_sizes, int n_in,
                              void* d_out, int out_size) {
    const float* a = (const float*)d_in[0];
    const float* b = (const float*)d_in[1];
    const float* w = (const float*)d_in[2];
    float* out = (float*)d_out;

    norm_kernel<<<dim3(NROWS, 2, 1), 128>>>(a, b, w);

    cudaFuncSetAttribute(gemm_kernel, cudaFuncAttributeMaxDynamicSharedMemorySize,
                         SMEM_BYTES);
    gemm_kernel<<<dim3(D_DIM / BN, D_DIM / BM, NBATCH), 128, SMEM_BYTES>>>(out);
}

// round 12
// speedup vs baseline: 1.2741x; 1.0524x over previous
#include <cuda_runtime.h>
#include <cuda_fp16.h>
#include <cstdint>
#include <cstddef>

#define D_DIM   1024
#define NBATCH  16
#define NROWS   (NBATCH * D_DIM)

#define BM 128
#define BN 128
#define BK 64                  // fp16 per K-chunk = 128B row (SW128)
#define NSTG 3
#define NITER (D_DIM / BK)     // 16

#define TILE_BYTES  (BM * 128)           // 16 KB
#define STAGE_BYTES (2 * TILE_BYTES)     // 32 KB
#define SMEM_BYTES  (NSTG * STAGE_BYTES) // 96 KB

// fp16 normalized-row scratch (allocation-free: __device__ globals)
__device__ __half g_ra[(size_t)NBATCH * D_DIM * D_DIM];
__device__ __half g_rb[(size_t)NBATCH * D_DIM * D_DIM];

// ---------------------------------------------------------------- helpers
static __device__ __forceinline__ uint32_t smem_u32(const void* p) {
    uint32_t a;
    asm("{ .reg .u64 t; cvta.to.shared.u64 t, %1; cvt.u32.u64 %0, t; }"
        : "=r"(a) : "l"(p));
    return a;
}
static __device__ __forceinline__ uint32_t sw128(uint32_t o) {
    return o ^ ((o >> 3) & 0x70u);
}
static __device__ __forceinline__ void cp16(uint32_t dst, const void* src) {
    asm volatile("cp.async.cg.shared.global [%0], [%1], 16;"
                 :: "r"(dst), "l"(src) : "memory");
}
static __device__ __forceinline__ void ldmatrix_x4(uint32_t* r, uint32_t addr) {
    asm volatile("ldmatrix.sync.aligned.m8n8.x4.shared.b16 {%0,%1,%2,%3}, [%4];"
                 : "=r"(r[0]), "=r"(r[1]), "=r"(r[2]), "=r"(r[3]) : "r"(addr));
}
static __device__ __forceinline__ void mma16816(float* d, const uint32_t* a,
                                                const uint32_t* b) {
    asm volatile(
        "mma.sync.aligned.m16n8k16.row.col.f32.f16.f16.f32 "
        "{%0,%1,%2,%3}, {%4,%5,%6,%7}, {%8,%9}, {%0,%1,%2,%3};"
        : "+f"(d[0]), "+f"(d[1]), "+f"(d[2]), "+f"(d[3])
        : "r"(a[0]), "r"(a[1]), "r"(a[2]), "r"(a[3]), "r"(b[0]), "r"(b[1]));
}

// ---------------------------------------------------------------- normalize
__global__ void __launch_bounds__(128) norm_kernel(const float* __restrict__ a,
                                                   const float* __restrict__ b,
                                                   const float* __restrict__ w) {
    const int row = blockIdx.x;
    const float* src = (blockIdx.y == 0) ? a : b;
    __half* dst = (blockIdx.y == 0) ? g_ra : g_rb;
    const int t = threadIdx.x;

    const float4* s4 = reinterpret_cast<const float4*>(src + (size_t)row * D_DIM);
    const float4* w4 = reinterpret_cast<const float4*>(w);

    float4 x0 = s4[t];       float4 w0 = w4[t];
    float4 x1 = s4[t + 128]; float4 w1 = w4[t + 128];
    float4 v0, v1;
    v0.x = x0.x * w0.x; v0.y = x0.y * w0.y; v0.z = x0.z * w0.z; v0.w = x0.w * w0.w;
    v1.x = x1.x * w1.x; v1.y = x1.y * w1.y; v1.z = x1.z * w1.z; v1.w = x1.w * w1.w;

    float sum = v0.x * v0.x + v0.y * v0.y + v0.z * v0.z + v0.w * v0.w
              + v1.x * v1.x + v1.y * v1.y + v1.z * v1.z + v1.w * v1.w;
#pragma unroll
    for (int o = 16; o > 0; o >>= 1) sum += __shfl_xor_sync(0xFFFFFFFFu, sum, o);

    __shared__ float red[4];
    if ((t & 31) == 0) red[t >> 5] = sum;
    __syncthreads();
    float tot = red[0] + red[1] + red[2] + red[3];
    float s = rsqrtf(fmaxf(tot, 1e-12f));

    __half2* d2 = reinterpret_cast<__half2*>(dst + (size_t)row * D_DIM);
    d2[2 * t + 0]         = __floats2half2_rn(v0.x * s, v0.y * s);
    d2[2 * t + 1]         = __floats2half2_rn(v0.z * s, v0.w * s);
    d2[2 * (t + 128) + 0] = __floats2half2_rn(v1.x * s, v1.y * s);
    d2[2 * (t + 128) + 1] = __floats2half2_rn(v1.z * s, v1.w * s);
}

// ---------------------------------------------------------------- GEMM
// 128x128 block tile, 4 warps (64x64 each), NSTG=3, reg double-buffered
// fragments, barrier rotated into the last MMA block of each iteration so the
// next iteration's first fragment loads hide under tensor work.
static __device__ __forceinline__ void load_stage(uint32_t stg,
                                                  const __half* gA, const __half* gB,
                                                  int kof, int tid) {
#pragma unroll
    for (int i = 0; i < 8; i++) {
        int q = i * 128 + tid;      // 1024 16B segments per operand tile
        int row = q >> 3;
        int colb = (q & 7) * 16;
        uint32_t so = sw128((uint32_t)(row * 128 + colb));
        cp16(stg + so,              (const char*)(gA + (size_t)row * D_DIM + kof) + colb);
        cp16(stg + TILE_BYTES + so, (const char*)(gB + (size_t)row * D_DIM + kof) + colb);
    }
    asm volatile("cp.async.commit_group;" ::: "memory");
}

__global__ void __launch_bounds__(128, 2) gemm_kernel(float* __restrict__ out) {
    extern __shared__ char smem[];
    const uint32_t sb = smem_u32(smem);
    const int tid  = threadIdx.x;
    const int wid  = tid >> 5;
    const int lane = tid & 31;
    const int wm   = wid & 1;        // 2 warps along M: 64 rows each
    const int wn   = wid >> 1;       // 2 warps along N: 64 cols each
    const int bn0   = blockIdx.x * BN;
    const int bm0   = blockIdx.y * BM;
    const int batch = blockIdx.z;

    const __half* gA = g_ra + (size_t)batch * (D_DIM * D_DIM) + (size_t)bm0 * D_DIM;
    const __half* gB = g_rb + (size_t)batch * (D_DIM * D_DIM) + (size_t)bn0 * D_DIM;

    float acc[4][8][4];
#pragma unroll
    for (int i = 0; i < 4; i++)
#pragma unroll
        for (int j = 0; j < 8; j++)
#pragma unroll
            for (int v = 0; v < 4; v++) acc[i][j][v] = 0.0f;

    // Swizzled ldmatrix bases; kb = kk*32 occupies bits 5-6 which are zero in
    // the unswizzled base, so sw128(base+kb) == sw128(base) ^ kb.
    const int aRow  = lane & 15;
    const int aColb = (lane >> 4) << 4;
    const int bRow  = ((lane >> 4) << 3) + (lane & 7);
    const int bColb = ((lane >> 3) & 1) << 4;

    uint32_t aOff[4], bOff[4];
#pragma unroll
    for (int mt = 0; mt < 4; mt++)
        aOff[mt] = sw128((uint32_t)((wm * 64 + mt * 16 + aRow) * 128 + aColb));
#pragma unroll
    for (int nq = 0; nq < 4; nq++)
        bOff[nq] = sw128((uint32_t)((wn * 64 + nq * 16 + bRow) * 128 + bColb))
                 + TILE_BYTES;

    // Double-buffered fragments
    uint32_t af[2][4][4], bf[2][4][4];

#define LD_FRAGS(buf, sT, kk)                                              \
    do {                                                                   \
        const uint32_t kb_ = (kk) * 32;                                    \
        _Pragma("unroll")                                                  \
        for (int mt_ = 0; mt_ < 4; mt_++)                                  \
            ldmatrix_x4(af[buf][mt_], (sT) + (aOff[mt_] ^ kb_));           \
        _Pragma("unroll")                                                  \
        for (int nq_ = 0; nq_ < 4; nq_++)                                  \
            ldmatrix_x4(bf[buf][nq_], (sT) + (bOff[nq_] ^ kb_));           \
    } while (0)

#define MMA_ALL(buf)                                                       \
    do {                                                                   \
        _Pragma("unroll")                                                  \
        for (int nq_ = 0; nq_ < 4; nq_++)                                  \
            _Pragma("unroll")                                              \
            for (int mt_ = 0; mt_ < 4; mt_++) {                            \
                mma16816(acc[mt_][2 * nq_ + 0], af[buf][mt_],              \
                         &bf[buf][nq_][0]);                                \
                mma16816(acc[mt_][2 * nq_ + 1], af[buf][mt_],              \
                         &bf[buf][nq_][2]);                                \
            }                                                              \
    } while (0)

    // prologue: 2 stages in flight; pre-arm buffer 0 with chunk0 kk=0
    load_stage(sb + 0 * STAGE_BYTES, gA, gB, 0 * BK, tid);
    load_stage(sb + 1 * STAGE_BYTES, gA, gB, 1 * BK, tid);
    asm volatile("cp.async.wait_group 1;" ::: "memory");   // chunk 0 resident
    __syncthreads();
    LD_FRAGS(0, sb + 0 * STAGE_BYTES, 0);

#pragma unroll 1
    for (int it = 0; it < NITER; it++) {
        const uint32_t sT = sb + (it % NSTG) * STAGE_BYTES;

        // Writes stage (it+2)%3 == (it-1)%3: last read in iteration it-1,
        // strictly before the barrier at the tail of iteration it-1.
        if (it + 2 < NITER)
            load_stage(sb + ((it + 2) % NSTG) * STAGE_BYTES, gA, gB, (it + 2) * BK, tid);
        else
            asm volatile("cp.async.commit_group;" ::: "memory");

        // buffer0 already holds kk=0 fragments (prefetched last iteration)
        LD_FRAGS(1, sT, 1);
        MMA_ALL(0);
        LD_FRAGS(0, sT, 2);
        MMA_ALL(1);
        LD_FRAGS(1, sT, 3);
        MMA_ALL(0);

        if (it + 1 < NITER) {
            // Committed groups now: 0..it+2; wait_group 1 => chunk it+1
            // resident. Barrier: all warps finished reading stage it%3 and
            // (it-1)%3 above, so iteration it+1 may overwrite (it-1)%3.
            asm volatile("cp.async.wait_group 1;" ::: "memory");
            __syncthreads();
            // Prefetch next iteration's kk=0 under the trailing MMA block.
            LD_FRAGS(0, sb + ((it + 1) % NSTG) * STAGE_BYTES, 0);
        }
        MMA_ALL(1);
    }

    // epilogue: c0,c1 -> (m = lane>>2, n = (lane&3)*2); c2,c3 -> m+8
    float* oB = out + (size_t)batch * (D_DIM * D_DIM);
#pragma unroll
    for (int mt = 0; mt < 4; mt++) {
        int row = bm0 + wm * 64 + mt * 16 + (lane >> 2);
#pragma unroll
        for (int nt = 0; nt < 8; nt++) {
            int col = bn0 + wn * 64 + nt * 8 + (lane & 3) * 2;
            *reinterpret_cast<float2*>(oB + (size_t)row * D_DIM + col) =
                make_float2(acc[mt][nt][0], acc[mt][nt][1]);
            *reinterpret_cast<float2*>(oB + (size_t)(row + 8) * D_DIM + col) =
                make_float2(acc[mt][nt][2], acc[mt][nt][3]);
        }
    }
}

// ---------------------------------------------------------------- launch
extern "C" void kernel_launch(void* const* d_in, const int* in_sizes, int n_in,
                              void* d_out, int out_size) {
    const float* a = (const float*)d_in[0];
    const float* b = (const float*)d_in[1];
    const float* w = (const float*)d_in[2];
    float* out = (float*)d_out;

    norm_kernel<<<dim3(NROWS, 2, 1), 128>>>(a, b, w);

    cudaFuncSetAttribute(gemm_kernel, cudaFuncAttributeMaxDynamicSharedMemorySize,
                         SMEM_BYTES);
    gemm_kernel<<<dim3(D_DIM / BN, D_DIM / BM, NBATCH), 128, SMEM_BYTES>>>(out);
}